// round 14
// baseline (speedup 1.0000x reference)
#include <cuda_runtime.h>
#include <cuda_fp16.h>
#include <float.h>
#include <stdint.h>

// ---------------------------------------------------------------------------
#define BB   32
#define CC   256
#define HWD  1024
#define KK   1024
#define NN   (BB * HWD)        // 32768
#define BM   128               // query rows per CTA
#define NCHUNK 32              // 8 nt * 4 kc (single fp16 product)

// SMEM layout for GEMM kernel
#define SM_A        0                   // [128 m][256 k] fp16 swizzled = 65536
#define SM_B        65536               // 4 stages x [128 n][64 k] fp16 = 65536
#define SM_B_BUF    16384
#define SM_SS       131072              // score staging half[128][136] = 34816
#define SS_PITCH    136
#define SMEM_TOTAL  (131072 + 128 * SS_PITCH * 2)   // 165888
#define SM_RED      SM_B                // reduction overlay (B ring dead then)
#define EPI_SMEM    (CC * BM * 4)       // 131072

// Certified error model (rigorous; see R10/R12):
//  register-path score err <= xn*(0.0021*sqrt(wsq)) + 0.05
//  fp16-stored score adds rounding; lower bounds use + 0.35.
#define E_CONST_REG   0.05f
#define E_CONST_STORE 0.35f

// ---------------------------------------------------------------------------
__device__ __align__(256) __half g_w1[KK * CC];              // w fp16 [n][k]
__device__ __align__(256) __half g_z1[NN * CC];              // z fp16 [m][k]
__device__ __align__(256) float  g_zt[NN * CC];              // z fp32 [m][c]
__device__ __align__(256) __half g_scores[(size_t)NN * KK];  // raw dots, fp16
__device__ float2   g_tab[KK];           // {wsq, 0.0021*sqrt(wsq)}
__device__ unsigned g_slmax_bits;        // max slope (float bits; atomicMax idempotent)
__device__ float    g_bestS[NN];
__device__ int      g_bestI[NN];
__device__ int      g_flag[NN];
__device__ int      g_ridx[NN];

// ---------------------------------------------------------------------------
__device__ __forceinline__ uint32_t smem_u32(const void* p) {
    return (uint32_t)__cvta_generic_to_shared(p);
}
__device__ __forceinline__ void cpa16(uint32_t s, const void* g) {
    asm volatile("cp.async.cg.shared.global [%0], [%1], 16;\n" :: "r"(s), "l"(g));
}
#define CPA_COMMIT() asm volatile("cp.async.commit_group;\n" ::: "memory")
#define CPA_WAIT(n)  asm volatile("cp.async.wait_group %0;\n" :: "n"(n) : "memory")

__device__ __forceinline__ void ldsm4(uint32_t* r, uint32_t addr) {
    asm volatile("ldmatrix.sync.aligned.m8n8.x4.shared.b16 {%0,%1,%2,%3}, [%4];"
                 : "=r"(r[0]), "=r"(r[1]), "=r"(r[2]), "=r"(r[3]) : "r"(addr));
}
__device__ __forceinline__ void mma16816(float* d, const uint32_t* a,
                                         uint32_t b0, uint32_t b1) {
    asm volatile("mma.sync.aligned.m16n8k16.row.col.f32.f16.f16.f32 "
                 "{%0,%1,%2,%3}, {%4,%5,%6,%7}, {%8,%9}, {%0,%1,%2,%3};"
                 : "+f"(d[0]), "+f"(d[1]), "+f"(d[2]), "+f"(d[3])
                 : "r"(a[0]), "r"(a[1]), "r"(a[2]), "r"(a[3]), "r"(b0), "r"(b1));
}

// ---------------------------------------------------------------------------
// Fused prep: w -> fp16 copy + per-code {wsq, slope} + global max slope.
__global__ void prep_w_kernel(const float* __restrict__ w) {
    int code = blockIdx.x * 8 + (threadIdx.x >> 5);
    int lane = threadIdx.x & 31;
    const float* row = w + (size_t)code * CC;
    float4 v0 = *(const float4*)(row + lane * 8);
    float4 v1 = *(const float4*)(row + lane * 8 + 4);
    float s = v0.x*v0.x + v0.y*v0.y + v0.z*v0.z + v0.w*v0.w
            + v1.x*v1.x + v1.y*v1.y + v1.z*v1.z + v1.w*v1.w;
    __half h[8];
    h[0]=__float2half_rn(v0.x); h[1]=__float2half_rn(v0.y);
    h[2]=__float2half_rn(v0.z); h[3]=__float2half_rn(v0.w);
    h[4]=__float2half_rn(v1.x); h[5]=__float2half_rn(v1.y);
    h[6]=__float2half_rn(v1.z); h[7]=__float2half_rn(v1.w);
    *(uint4*)(g_w1 + (size_t)code * CC + lane * 8) = *(uint4*)h;
    #pragma unroll
    for (int o = 16; o; o >>= 1) s += __shfl_down_sync(0xffffffffu, s, o);
    if (lane == 0) {
        float slope = 0.0021f * sqrtf(s);
        g_tab[code] = make_float2(s, slope);
        atomicMax(&g_slmax_bits, __float_as_uint(slope));
    }
}

// Transpose z: z[b][c][hw] -> g_z1 fp16 [m][c] and g_zt fp32 [m][c]
__global__ void zprep_kernel(const float* __restrict__ z) {
    __shared__ float t[32][33];
    int c0  = blockIdx.x * 32;
    int hw0 = blockIdx.y * 32;
    int b   = blockIdx.z;
    int x = threadIdx.x, y0 = threadIdx.y;     // 32 x 8
    const float* zb = z + ((size_t)b * CC) * HWD;
    #pragma unroll
    for (int yy = 0; yy < 32; yy += 8)
        t[y0 + yy][x] = zb[(size_t)(c0 + y0 + yy) * HWD + hw0 + x];
    __syncthreads();
    #pragma unroll
    for (int yy = 0; yy < 32; yy += 8) {
        int hwl = y0 + yy;
        float v = t[x][hwl];
        size_t o = (size_t)(b * HWD + hw0 + hwl) * CC + c0 + x;
        g_zt[o] = v;
        g_z1[o] = __float2half_rn(v);
    }
}

// ---------------------------------------------------------------------------
__device__ __forceinline__ void load_b_chunk(uint32_t Bbase, int c, int slot, int tid) {
    int nt = c >> 2, kc = c & 3;
    const __half* base = g_w1 + ((size_t)(nt * 128) << 8) + (kc << 6);
    uint32_t dst = Bbase + slot * SM_B_BUF;
    #pragma unroll
    for (int j = 0; j < 2; ++j) {
        int gi = j * 512 + tid;
        int r = gi >> 3, g = gi & 7;
        cpa16(dst + r * 128 + ((g ^ (r & 7)) << 4),
              base + ((size_t)r << 8) + (g << 3));
    }
}

// ---------------------------------------------------------------------------
// 1-product HMMA GEMM (512 thr, warp grid 4m x 4n, warp tile 32m x 32n).
// Stores fp16 scores + top-2 fold + uniform-bound certificate.
__global__ __launch_bounds__(512, 1)
void vq_gemm_kernel() {
    extern __shared__ __align__(1024) char smem[];
    const int tid  = threadIdx.x;
    const int lane = tid & 31;
    const int wid  = tid >> 5;
    const int wm   = wid >> 2;     // 0..3 : m-warp (32 rows)
    const int wn   = wid & 3;      // 0..3 : n-warp (32 cols)

    const int n0 = blockIdx.x * BM;

    const uint32_t sbase = smem_u32(smem);
    const uint32_t Abase = sbase + SM_A;
    const uint32_t Bbase = sbase + SM_B;

    #pragma unroll
    for (int j = 0; j < 8; ++j) {
        int gi = j * 512 + tid;            // 4096 granules
        int m = gi >> 5, g = gi & 31;
        cpa16(Abase + m * 512 + ((g ^ (m & 7)) << 4),
              g_z1 + ((size_t)(n0 + m) << 8) + (g << 3));
    }
    load_b_chunk(Bbase, 0, 0, tid);
    CPA_COMMIT();
    load_b_chunk(Bbase, 1, 1, tid);
    CPA_COMMIT();
    load_b_chunk(Bbase, 2, 2, tid);
    CPA_COMMIT();

    const uint32_t a_row = wm * 32 + (lane & 15);
    const uint32_t a_ghi = lane >> 4;
    const uint32_t a_rx  = a_row & 7;
    const uint32_t a_addr0 = Abase + a_row * 512;

    uint32_t b_addr0[2], b_gx[2];
    #pragma unroll
    for (int bl = 0; bl < 2; ++bl) {
        uint32_t nr = wn * 32 + bl * 16 + (lane & 15);
        b_addr0[bl] = Bbase + nr * 128;
        b_gx[bl] = nr & 7;
    }

    // top-2 state per row-slot s: row = wm*32 + (lane>>2) + (s>>1)*16 + (s&1)*8
    float bv1[4], bv2[4];
    int   bi1[4];
    #pragma unroll
    for (int s = 0; s < 4; ++s) { bv1[s] = FLT_MAX; bv2[s] = FLT_MAX; bi1[s] = 0; }

    float acc[2][4][4];

    for (int c = 0; c < NCHUNK; ++c) {
        const int nt   = c >> 2;
        const int kc   = c & 3;
        const int slot = c & 3;

        if (c + 2 < NCHUNK)      CPA_WAIT(2);
        else if (c + 1 < NCHUNK) CPA_WAIT(1);
        else                     CPA_WAIT(0);
        __syncthreads();
        if (c + 3 < NCHUNK) {
            load_b_chunk(Bbase, c + 3, (c + 3) & 3, tid);
            CPA_COMMIT();
        }

        if (kc == 0) {
            #pragma unroll
            for (int i = 0; i < 2; ++i)
                #pragma unroll
                for (int j = 0; j < 4; ++j)
                    #pragma unroll
                    for (int d = 0; d < 4; ++d) acc[i][j][d] = 0.f;
        }

        #pragma unroll
        for (int kh = 0; kh < 2; ++kh) {
            #pragma unroll
            for (int ks2 = 0; ks2 < 2; ++ks2) {
                const int ks = kh * 2 + ks2;
                uint32_t bfr[2][4];
                #pragma unroll
                for (int bl = 0; bl < 2; ++bl) {
                    uint32_t g = ks * 2 + a_ghi;
                    ldsm4(bfr[bl], b_addr0[bl] + slot * SM_B_BUF + ((g ^ b_gx[bl]) << 4));
                }
                uint32_t g = kc * 8 + ks * 2 + a_ghi;
                uint32_t off = ((g ^ a_rx) << 4);
                uint32_t afr[2][4];
                ldsm4(afr[0], a_addr0 + off);
                ldsm4(afr[1], a_addr0 + 8192 + off);
                #pragma unroll
                for (int mf = 0; mf < 2; ++mf)
                    #pragma unroll
                    for (int bl = 0; bl < 2; ++bl) {
                        mma16816(acc[mf][bl * 2],     afr[mf], bfr[bl][0], bfr[bl][2]);
                        mma16816(acc[mf][bl * 2 + 1], afr[mf], bfr[bl][1], bfr[bl][3]);
                    }
            }
        }

        if (kc == 3) {
            // top-2 fold of approx scores (fp32 accumulators)
            #pragma unroll
            for (int nf = 0; nf < 4; ++nf) {
                int k0 = nt * 128 + wn * 32 + ((lane & 3) << 1) + nf * 8;
                float4 tb = *(const float4*)&g_tab[k0];   // wsq0, sl0, wsq1, sl1
                #pragma unroll
                for (int mf = 0; mf < 2; ++mf)
                    #pragma unroll
                    for (int d = 0; d < 4; ++d) {
                        const int s = mf * 2 + (d >> 1);
                        const int k = k0 + (d & 1);
                        const float wsq = (d & 1) ? tb.z : tb.x;
                        float sc = wsq - 2.f * acc[mf][nf][d];
                        if (sc < bv1[s]) { bv2[s] = bv1[s]; bv1[s] = sc; bi1[s] = k; }
                        else if (sc < bv2[s]) bv2[s] = sc;
                    }
            }
            // stage fp16 scores, then coalesced global store
            __half* ss = (__half*)(smem + SM_SS);
            int r0  = wm * 32 + (lane >> 2);
            int col0 = wn * 32 + ((lane & 3) << 1);
            #pragma unroll
            for (int mf = 0; mf < 2; ++mf)
                #pragma unroll
                for (int nf = 0; nf < 4; ++nf) {
                    int r = r0 + mf * 16;
                    int col = col0 + nf * 8;
                    *(__half2*)&ss[r * SS_PITCH + col] =
                        __floats2half2_rn(acc[mf][nf][0], acc[mf][nf][1]);
                    *(__half2*)&ss[(r + 8) * SS_PITCH + col] =
                        __floats2half2_rn(acc[mf][nf][2], acc[mf][nf][3]);
                }
            __syncthreads();
            {
                int r = tid >> 2, part = tid & 3;
                const uint4* src = (const uint4*)(smem + SM_SS + r * (SS_PITCH * 2) + part * 64);
                uint4* dst = (uint4*)(g_scores + (((size_t)(n0 + r)) << 10) + (nt << 7) + part * 32);
                #pragma unroll
                for (int j = 0; j < 4; ++j) dst[j] = src[j];
            }
        }
    }
    __syncthreads();   // B ring dead

    // merge top-2 across the 4 lanes sharing each row, then across 4 n-warps
    float* redv1 = (float*)(smem + SM_RED);             // [128][4]
    int*   redi1 = (int*)  (smem + SM_RED + 2048);
    float* redv2 = (float*)(smem + SM_RED + 4096);

    #pragma unroll
    for (int s = 0; s < 4; ++s) {
        float v1 = bv1[s], v2 = bv2[s];
        int   i1 = bi1[s];
        #pragma unroll
        for (int msk = 1; msk <= 2; msk <<= 1) {
            float ov1 = __shfl_xor_sync(0xffffffffu, v1, msk);
            int   oi1 = __shfl_xor_sync(0xffffffffu, i1, msk);
            float ov2 = __shfl_xor_sync(0xffffffffu, v2, msk);
            if (ov1 < v1) { v2 = fminf(v1, ov2); v1 = ov1; i1 = oi1; }
            else          { v2 = fminf(v2, ov1); }
        }
        if ((lane & 3) == 0) {
            int row = wm * 32 + (lane >> 2) + (s >> 1) * 16 + ((s & 1) << 3);
            redv1[row * 4 + wn] = v1;
            redi1[row * 4 + wn] = i1;
            redv2[row * 4 + wn] = v2;
        }
    }
    __syncthreads();

    if (tid < BM) {
        float v1 = redv1[tid * 4], v2 = redv2[tid * 4];
        int   i1 = redi1[tid * 4];
        #pragma unroll
        for (int j = 1; j < 4; ++j) {
            float ov1 = redv1[tid * 4 + j];
            int   oi1 = redi1[tid * 4 + j];
            float ov2 = redv2[tid * 4 + j];
            if (ov1 < v1) { v2 = fminf(v1, ov2); v1 = ov1; i1 = oi1; }
            else          { v2 = fminf(v2, ov1); }
        }
        // xn from the resident fp16 A row (rigorous slack for fp16 rounding)
        float xs = 0.f;
        #pragma unroll
        for (int g = 0; g < 32; ++g) {
            uint4 v = *(const uint4*)(smem + SM_A + tid * 512 + (((uint32_t)g ^ (tid & 7)) << 4));
            float2 f;
            f = __half22float2(*(__half2*)&v.x); xs += f.x*f.x + f.y*f.y;
            f = __half22float2(*(__half2*)&v.y); xs += f.x*f.x + f.y*f.y;
            f = __half22float2(*(__half2*)&v.z); xs += f.x*f.x + f.y*f.y;
            f = __half22float2(*(__half2*)&v.w); xs += f.x*f.x + f.y*f.y;
        }
        float xn = sqrtf(xs) * 1.0006f + 0.01f;
        float E  = fmaf(xn, __uint_as_float(g_slmax_bits), E_CONST_REG);
        int m = n0 + tid;
        g_bestS[m] = v1;
        g_bestI[m] = i1;
        g_ridx[m]  = i1;
        g_flag[m]  = (v2 - v1 > 2.f * E) ? 0 : 1;
    }
}

// ---------------------------------------------------------------------------
// Flag-gated single-pass select: prune stored fp16 scores vs GEMM-seeded
// threshold, exact fp32 rescore of the few candidates.
__global__ __launch_bounds__(256)
void select_kernel(const float* __restrict__ w) {
    const int lane = threadIdx.x & 31;
    const int m = blockIdx.x * 8 + (threadIdx.x >> 5);
    if (__ldg(&g_flag[m]) == 0) return;

    // z row (fp32) + norm bound
    float zv[8]; float xsq = 0.f;
    const float* zr = g_zt + ((size_t)m << 8);
    #pragma unroll
    for (int j = 0; j < 8; ++j) { zv[j] = zr[j * 32 + lane]; xsq = fmaf(zv[j], zv[j], xsq); }
    #pragma unroll
    for (int o = 16; o; o >>= 1) xsq += __shfl_xor_sync(0xffffffffu, xsq, o);
    const float xn = sqrtf(xsq) * 1.0001f + 0.01f;

    // threshold from GEMM's approx best (register-path error bound)
    const int   bi0 = __ldg(&g_bestI[m]);
    const float T   = __ldg(&g_bestS[m]) + fmaf(xn, __ldg(&g_tab[bi0].y), E_CONST_REG);

    const uint32_t* sp = (const uint32_t*)(g_scores + ((size_t)m << 10));
    float best = FLT_MAX; int bi = 0x7fffffff;
    #pragma unroll 4
    for (int i = 0; i < 16; ++i) {
        uint32_t sv = sp[i * 32 + lane];
        int k0 = (i * 32 + lane) * 2;
        float4 tb = *(const float4*)&g_tab[k0];           // wsq0, sl0, wsq1, sl1
        __half2 h = *(__half2*)&sv;
        float s0 = tb.x - 2.f * __half2float(h.x);
        float s1 = tb.z - 2.f * __half2float(h.y);
        bool c0 = (s0 - fmaf(xn, tb.y, E_CONST_STORE)) <= T;
        bool c1 = (s1 - fmaf(xn, tb.w, E_CONST_STORE)) <= T;
        #pragma unroll
        for (int half = 0; half < 2; ++half) {
            uint32_t mk = __ballot_sync(0xffffffffu, half ? c1 : c0);
            while (mk) {
                int src = __ffs(mk) - 1; mk &= mk - 1;
                int k = __shfl_sync(0xffffffffu, k0, src) + half;
                float dot = 0.f;
                const float* wr = w + ((size_t)k << 8);
                #pragma unroll
                for (int j = 0; j < 8; ++j)
                    dot = fmaf(zv[j], __ldg(&wr[j * 32 + lane]), dot);
                #pragma unroll
                for (int o = 16; o; o >>= 1) dot += __shfl_xor_sync(0xffffffffu, dot, o);
                float se = __ldg(&g_tab[k].x) - 2.f * dot;
                if (se < best || (se == best && k < bi)) { best = se; bi = k; }
            }
        }
    }
    if (lane == 0) g_ridx[m] = bi;
}

// ---------------------------------------------------------------------------
__global__ __launch_bounds__(512)
void epilogue_kernel(const float* __restrict__ z, const float* __restrict__ w,
                     float* __restrict__ out) {
    extern __shared__ float qs[];       // [256 c][128 m]
    const int tid = threadIdx.x;
    const int n0  = blockIdx.x * BM;
    const int b   = n0 >> 10;
    const int hw0 = n0 & (HWD - 1);

    {
        int m = tid & 127, cpart = tid >> 7;
        const float4* wr = (const float4*)(w + ((size_t)g_ridx[n0 + m] << 8) + cpart * 64);
        #pragma unroll
        for (int g = 0; g < 16; ++g) {
            float4 v = wr[g];
            int cq = cpart * 64 + g * 4;
            qs[(cq + 0) * BM + m] = v.x;
            qs[(cq + 1) * BM + m] = v.y;
            qs[(cq + 2) * BM + m] = v.z;
            qs[(cq + 3) * BM + m] = v.w;
        }
    }
    __syncthreads();
    {
        float* out_bar = out + (size_t)NN * CC;
        const int cg = tid >> 5;
        const int r4 = (tid & 31) * 4;
        #pragma unroll 4
        for (int cc = 0; cc < 16; ++cc) {
            int cq = cg * 16 + cc;
            size_t zo = ((size_t)(b * CC + cq)) * HWD + hw0 + r4;
            float4 zvv = *(const float4*)(z + zo);
            float4 q   = *(const float4*)(qs + cq * BM + r4);
            float4 co;
            co.x = zvv.x + (q.x - zvv.x);
            co.y = zvv.y + (q.y - zvv.y);
            co.z = zvv.z + (q.z - zvv.z);
            co.w = zvv.w + (q.w - zvv.w);
            *(float4*)(out + zo)     = co;
            *(float4*)(out_bar + zo) = q;
        }
    }
}

// ---------------------------------------------------------------------------
extern "C" void kernel_launch(void* const* d_in, const int* in_sizes, int n_in,
                              void* d_out, int out_size) {
    const float* z = (const float*)d_in[0];
    const float* w = (const float*)d_in[1];
    if (n_in >= 2 && in_sizes[0] == KK * CC && in_sizes[1] == NN * CC) {
        const float* t = z; z = w; w = t;
    }
    float* out = (float*)d_out;

    static bool attr_set = false;
    if (!attr_set) {
        cudaFuncSetAttribute(vq_gemm_kernel, cudaFuncAttributeMaxDynamicSharedMemorySize,
                             SMEM_TOTAL);
        cudaFuncSetAttribute(epilogue_kernel, cudaFuncAttributeMaxDynamicSharedMemorySize,
                             EPI_SMEM);
        attr_set = true;
    }

    prep_w_kernel<<<KK / 8, 256>>>(w);
    zprep_kernel<<<dim3(CC / 32, HWD / 32, BB), dim3(32, 8)>>>(z);
    vq_gemm_kernel<<<NN / BM, 512, SMEM_TOTAL>>>();
    select_kernel<<<NN / 8, 256>>>(w);
    epilogue_kernel<<<NN / BM, 512, EPI_SMEM>>>(z, w, out);
}

// round 15
// speedup vs baseline: 1.1876x; 1.1876x over previous
#include <cuda_runtime.h>
#include <cuda_fp16.h>
#include <float.h>
#include <stdint.h>

// ---------------------------------------------------------------------------
#define BB   32
#define CC   256
#define HWD  1024
#define KK   1024
#define NN   (BB * HWD)        // 32768
#define BM   128               // query rows per CTA
#define NCHUNK 32              // 8 nt * 4 kc (single fp16 product)

// SMEM layout for GEMM kernel
#define SM_A        0                   // [128 m][256 k] fp16 swizzled = 65536
#define SM_B        65536               // 4 stages x [128 n][64 k] fp16 = 65536
#define SM_B_BUF    16384
#define SM_SS       131072              // score staging half[128][136] = 34816
#define SS_PITCH    136
#define SMEM_TOTAL  (131072 + 128 * SS_PITCH * 2)   // 165888
#define EPI_SMEM    (CC * BM * 4)                   // 131072

// Certified bound (validated in R10: slope 0.0035*sqrt(wsq), const 0.2, rel_err 0.0)
#define E_CONST 0.2f

// ---------------------------------------------------------------------------
// Device scratch (static globals — no allocation)
__device__ __align__(256) __half g_w1[KK * CC];              // w fp16 [n][k]
__device__ __align__(256) __half g_z1[NN * CC];              // z fp16 [m][k]
__device__ __align__(256) float  g_zt[NN * CC];              // z fp32 [m][c]
__device__ __align__(256) __half g_scores[(size_t)NN * KK];  // raw dots, fp16
__device__ float    g_wsq[KK];
__device__ unsigned g_slmax_bits;        // max over k of 0.0035*sqrt(wsq_k), float bits
__device__ float    g_xnp[8 * NN];       // per-row partial |x|^2 (8 c-blocks)
__device__ int      g_ridx[NN];

// ---------------------------------------------------------------------------
__device__ __forceinline__ uint32_t smem_u32(const void* p) {
    return (uint32_t)__cvta_generic_to_shared(p);
}
__device__ __forceinline__ void cpa16(uint32_t s, const void* g) {
    asm volatile("cp.async.cg.shared.global [%0], [%1], 16;\n" :: "r"(s), "l"(g));
}
#define CPA_COMMIT() asm volatile("cp.async.commit_group;\n" ::: "memory")
#define CPA_WAIT(n)  asm volatile("cp.async.wait_group %0;\n" :: "n"(n) : "memory")

__device__ __forceinline__ void ldsm4(uint32_t* r, uint32_t addr) {
    asm volatile("ldmatrix.sync.aligned.m8n8.x4.shared.b16 {%0,%1,%2,%3}, [%4];"
                 : "=r"(r[0]), "=r"(r[1]), "=r"(r[2]), "=r"(r[3]) : "r"(addr));
}
__device__ __forceinline__ void mma16816(float* d, const uint32_t* a,
                                         uint32_t b0, uint32_t b1) {
    asm volatile("mma.sync.aligned.m16n8k16.row.col.f32.f16.f16.f32 "
                 "{%0,%1,%2,%3}, {%4,%5,%6,%7}, {%8,%9}, {%0,%1,%2,%3};"
                 : "+f"(d[0]), "+f"(d[1]), "+f"(d[2]), "+f"(d[3])
                 : "r"(a[0]), "r"(a[1]), "r"(a[2]), "r"(a[3]), "r"(b0), "r"(b1));
}

// ---------------------------------------------------------------------------
// Prep: w -> fp16 copy + wsq + global max slope. One warp per code.
__global__ void prep_w_kernel(const float* __restrict__ w) {
    int code = blockIdx.x * 8 + (threadIdx.x >> 5);
    int lane = threadIdx.x & 31;
    const float* row = w + (size_t)code * CC;
    float4 v0 = *(const float4*)(row + lane * 8);
    float4 v1 = *(const float4*)(row + lane * 8 + 4);
    float s = v0.x*v0.x + v0.y*v0.y + v0.z*v0.z + v0.w*v0.w
            + v1.x*v1.x + v1.y*v1.y + v1.z*v1.z + v1.w*v1.w;
    __half h[8];
    h[0]=__float2half_rn(v0.x); h[1]=__float2half_rn(v0.y);
    h[2]=__float2half_rn(v0.z); h[3]=__float2half_rn(v0.w);
    h[4]=__float2half_rn(v1.x); h[5]=__float2half_rn(v1.y);
    h[6]=__float2half_rn(v1.z); h[7]=__float2half_rn(v1.w);
    *(uint4*)(g_w1 + (size_t)code * CC + lane * 8) = *(uint4*)h;
    #pragma unroll
    for (int o = 16; o; o >>= 1) s += __shfl_down_sync(0xffffffffu, s, o);
    if (lane == 0) {
        g_wsq[code] = s;
        atomicMax(&g_slmax_bits, __float_as_uint(0.0035f * sqrtf(s)));
    }
}

// Transpose z -> g_z1 fp16 / g_zt fp32, plus per-row 32c-block norm partials.
__global__ void zprep_kernel(const float* __restrict__ z) {
    __shared__ float t[32][33];
    int c0  = blockIdx.x * 32;
    int hw0 = blockIdx.y * 32;
    int b   = blockIdx.z;
    int x = threadIdx.x, y0 = threadIdx.y;     // 32 x 8; warp = fixed y0
    const float* zb = z + ((size_t)b * CC) * HWD;
    #pragma unroll
    for (int yy = 0; yy < 32; yy += 8)
        t[y0 + yy][x] = zb[(size_t)(c0 + y0 + yy) * HWD + hw0 + x];
    __syncthreads();
    #pragma unroll
    for (int yy = 0; yy < 32; yy += 8) {
        int hwl = y0 + yy;
        float v = t[x][hwl];
        size_t o = (size_t)(b * HWD + hw0 + hwl) * CC + c0 + x;
        g_zt[o] = v;
        g_z1[o] = __float2half_rn(v);
        float p = v * v;
        #pragma unroll
        for (int sh = 16; sh; sh >>= 1) p += __shfl_xor_sync(0xffffffffu, p, sh);
        if (x == 0)
            g_xnp[(c0 >> 5) * NN + b * HWD + hw0 + hwl] = p;
    }
}

// ---------------------------------------------------------------------------
__device__ __forceinline__ void load_b_chunk(uint32_t Bbase, int c, int slot, int tid) {
    int nt = c >> 2, kc = c & 3;
    const __half* base = g_w1 + ((size_t)(nt * 128) << 8) + (kc << 6);
    uint32_t dst = Bbase + slot * SM_B_BUF;
    #pragma unroll
    for (int j = 0; j < 2; ++j) {
        int gi = j * 512 + tid;
        int r = gi >> 3, g = gi & 7;
        cpa16(dst + r * 128 + ((g ^ (r & 7)) << 4),
              base + ((size_t)r << 8) + (g << 3));
    }
}

// ---------------------------------------------------------------------------
// Bare 1-product HMMA GEMM (R10's measured-75us config): stores fp16 scores.
__global__ __launch_bounds__(512, 1)
void vq_gemm_kernel() {
    extern __shared__ __align__(1024) char smem[];
    const int tid  = threadIdx.x;
    const int lane = tid & 31;
    const int wid  = tid >> 5;
    const int wm   = wid >> 2;
    const int wn   = wid & 3;

    const int n0 = blockIdx.x * BM;

    const uint32_t sbase = smem_u32(smem);
    const uint32_t Abase = sbase + SM_A;
    const uint32_t Bbase = sbase + SM_B;

    #pragma unroll
    for (int j = 0; j < 8; ++j) {
        int gi = j * 512 + tid;
        int m = gi >> 5, g = gi & 31;
        cpa16(Abase + m * 512 + ((g ^ (m & 7)) << 4),
              g_z1 + ((size_t)(n0 + m) << 8) + (g << 3));
    }
    load_b_chunk(Bbase, 0, 0, tid);
    CPA_COMMIT();
    load_b_chunk(Bbase, 1, 1, tid);
    CPA_COMMIT();
    load_b_chunk(Bbase, 2, 2, tid);
    CPA_COMMIT();

    const uint32_t a_row = wm * 32 + (lane & 15);
    const uint32_t a_ghi = lane >> 4;
    const uint32_t a_rx  = a_row & 7;
    const uint32_t a_addr0 = Abase + a_row * 512;

    uint32_t b_addr0[2], b_gx[2];
    #pragma unroll
    for (int bl = 0; bl < 2; ++bl) {
        uint32_t nr = wn * 32 + bl * 16 + (lane & 15);
        b_addr0[bl] = Bbase + nr * 128;
        b_gx[bl] = nr & 7;
    }

    float acc[2][4][4];

    for (int c = 0; c < NCHUNK; ++c) {
        const int nt   = c >> 2;
        const int kc   = c & 3;
        const int slot = c & 3;

        if (c + 2 < NCHUNK)      CPA_WAIT(2);
        else if (c + 1 < NCHUNK) CPA_WAIT(1);
        else                     CPA_WAIT(0);
        __syncthreads();
        if (c + 3 < NCHUNK) {
            load_b_chunk(Bbase, c + 3, (c + 3) & 3, tid);
            CPA_COMMIT();
        }

        if (kc == 0) {
            #pragma unroll
            for (int i = 0; i < 2; ++i)
                #pragma unroll
                for (int j = 0; j < 4; ++j)
                    #pragma unroll
                    for (int d = 0; d < 4; ++d) acc[i][j][d] = 0.f;
        }

        #pragma unroll
        for (int kh = 0; kh < 2; ++kh) {
            #pragma unroll
            for (int ks2 = 0; ks2 < 2; ++ks2) {
                const int ks = kh * 2 + ks2;
                uint32_t bfr[2][4];
                #pragma unroll
                for (int bl = 0; bl < 2; ++bl) {
                    uint32_t g = ks * 2 + a_ghi;
                    ldsm4(bfr[bl], b_addr0[bl] + slot * SM_B_BUF + ((g ^ b_gx[bl]) << 4));
                }
                uint32_t g = kc * 8 + ks * 2 + a_ghi;
                uint32_t off = ((g ^ a_rx) << 4);
                uint32_t afr[2][4];
                ldsm4(afr[0], a_addr0 + off);
                ldsm4(afr[1], a_addr0 + 8192 + off);
                #pragma unroll
                for (int mf = 0; mf < 2; ++mf)
                    #pragma unroll
                    for (int bl = 0; bl < 2; ++bl) {
                        mma16816(acc[mf][bl * 2],     afr[mf], bfr[bl][0], bfr[bl][2]);
                        mma16816(acc[mf][bl * 2 + 1], afr[mf], bfr[bl][1], bfr[bl][3]);
                    }
            }
        }

        if (kc == 3) {
            __half* ss = (__half*)(smem + SM_SS);
            int r0  = wm * 32 + (lane >> 2);
            int col0 = wn * 32 + ((lane & 3) << 1);
            #pragma unroll
            for (int mf = 0; mf < 2; ++mf)
                #pragma unroll
                for (int nf = 0; nf < 4; ++nf) {
                    int r = r0 + mf * 16;
                    int col = col0 + nf * 8;
                    *(__half2*)&ss[r * SS_PITCH + col] =
                        __floats2half2_rn(acc[mf][nf][0], acc[mf][nf][1]);
                    *(__half2*)&ss[(r + 8) * SS_PITCH + col] =
                        __floats2half2_rn(acc[mf][nf][2], acc[mf][nf][3]);
                }
            __syncthreads();
            {
                int r = tid >> 2, part = tid & 3;
                const uint4* src = (const uint4*)(smem + SM_SS + r * (SS_PITCH * 2) + part * 64);
                uint4* dst = (uint4*)(g_scores + (((size_t)(n0 + r)) << 10) + (nt << 7) + part * 32);
                #pragma unroll
                for (int j = 0; j < 4; ++j) dst[j] = src[j];
            }
        }
    }
}

// ---------------------------------------------------------------------------
// Argmin + certify + (rare) exact rescore. One warp per row.
__global__ __launch_bounds__(256)
void argmin_kernel(const float* __restrict__ w) {
    __shared__ float s_wsq[KK];
    const int tid  = threadIdx.x;
    const int lane = tid & 31;
    const int m = blockIdx.x * 8 + (tid >> 5);
    for (int i = tid; i < KK; i += 256) s_wsq[i] = g_wsq[i];
    __syncthreads();

    // xn from per-row partials
    float xsq = (lane < 8) ? __ldg(&g_xnp[lane * NN + m]) : 0.f;
    #pragma unroll
    for (int o = 4; o; o >>= 1) xsq += __shfl_xor_sync(0xffffffffu, xsq, o);
    xsq = __shfl_sync(0xffffffffu, xsq, 0);
    const float xn = sqrtf(xsq) * 1.0001f + 0.01f;
    const float E  = fmaf(xn, __uint_as_float(g_slmax_bits), E_CONST);

    // load scores (coalesced) + compute approx scores in fp32
    const uint32_t* sp = (const uint32_t*)(g_scores + ((size_t)m << 10));
    float s[32];
    #pragma unroll
    for (int i = 0; i < 16; ++i) {
        uint32_t sv = sp[i * 32 + lane];
        int k0 = (i * 32 + lane) * 2;
        float2 wq = *(const float2*)&s_wsq[k0];
        float2 f  = __half22float2(*(__half2*)&sv);
        s[2*i]   = wq.x - 2.f * f.x;
        s[2*i+1] = wq.y - 2.f * f.y;
    }

    // per-lane min + index, then warp reduce
    float bestv = FLT_MAX; int besti = 0;
    #pragma unroll
    for (int i = 0; i < 16; ++i) {
        int k0 = (i * 32 + lane) * 2;
        if (s[2*i]   < bestv) { bestv = s[2*i];   besti = k0; }
        if (s[2*i+1] < bestv) { bestv = s[2*i+1]; besti = k0 + 1; }
    }
    #pragma unroll
    for (int o = 16; o; o >>= 1) {
        float ov = __shfl_xor_sync(0xffffffffu, bestv, o);
        int   oi = __shfl_xor_sync(0xffffffffu, besti, o);
        if (ov < bestv) { bestv = ov; besti = oi; }
    }

    // candidate mask per lane (bit x = score i=x>>1, d=x&1)
    const float T = bestv + 2.f * E;
    uint32_t cm = 0;
    #pragma unroll
    for (int i = 0; i < 16; ++i) {
        cm |= (s[2*i]   <= T) ? (1u << (2*i))     : 0u;
        cm |= (s[2*i+1] <= T) ? (1u << (2*i + 1)) : 0u;
    }
    int cnt = __popc(cm);
    #pragma unroll
    for (int o = 16; o; o >>= 1) cnt += __shfl_xor_sync(0xffffffffu, cnt, o);

    if (cnt == 1) {
        // unique candidate == certified exact argmin
        if (lane == 0) g_ridx[m] = besti;
        return;
    }

    // exact fp32 rescore of the candidate set (provably contains argmin)
    float zv[8];
    const float* zr = g_zt + ((size_t)m << 8);
    #pragma unroll
    for (int j = 0; j < 8; ++j) zv[j] = zr[j * 32 + lane];

    float best = FLT_MAX; int bi = 0x7fffffff;
    uint32_t act = __ballot_sync(0xffffffffu, cm != 0);
    while (act) {
        int src = __ffs(act) - 1; act &= act - 1;
        uint32_t mk = __shfl_sync(0xffffffffu, cm, src);
        while (mk) {
            int x = __ffs(mk) - 1; mk &= mk - 1;
            int k = (((x >> 1) * 32 + src) << 1) + (x & 1);
            float dot = 0.f;
            const float* wr = w + ((size_t)k << 8);
            #pragma unroll
            for (int j = 0; j < 8; ++j)
                dot = fmaf(zv[j], __ldg(&wr[j * 32 + lane]), dot);
            #pragma unroll
            for (int o = 16; o; o >>= 1) dot += __shfl_xor_sync(0xffffffffu, dot, o);
            float se = s_wsq[k] - 2.f * dot;
            if (se < best || (se == best && k < bi)) { best = se; bi = k; }
        }
    }
    if (lane == 0) g_ridx[m] = bi;
}

// ---------------------------------------------------------------------------
__global__ __launch_bounds__(512)
void epilogue_kernel(const float* __restrict__ z, const float* __restrict__ w,
                     float* __restrict__ out) {
    extern __shared__ float qs[];       // [256 c][128 m]
    const int tid = threadIdx.x;
    const int n0  = blockIdx.x * BM;
    const int b   = n0 >> 10;
    const int hw0 = n0 & (HWD - 1);

    {
        int m = tid & 127, cpart = tid >> 7;
        const float4* wr = (const float4*)(w + ((size_t)g_ridx[n0 + m] << 8) + cpart * 64);
        #pragma unroll
        for (int g = 0; g < 16; ++g) {
            float4 v = wr[g];
            int cq = cpart * 64 + g * 4;
            qs[(cq + 0) * BM + m] = v.x;
            qs[(cq + 1) * BM + m] = v.y;
            qs[(cq + 2) * BM + m] = v.z;
            qs[(cq + 3) * BM + m] = v.w;
        }
    }
    __syncthreads();
    {
        float* out_bar = out + (size_t)NN * CC;
        const int cg = tid >> 5;
        const int r4 = (tid & 31) * 4;
        #pragma unroll 4
        for (int cc = 0; cc < 16; ++cc) {
            int cq = cg * 16 + cc;
            size_t zo = ((size_t)(b * CC + cq)) * HWD + hw0 + r4;
            float4 zvv = *(const float4*)(z + zo);
            float4 q   = *(const float4*)(qs + cq * BM + r4);
            float4 co;
            co.x = zvv.x + (q.x - zvv.x);
            co.y = zvv.y + (q.y - zvv.y);
            co.z = zvv.z + (q.z - zvv.z);
            co.w = zvv.w + (q.w - zvv.w);
            *(float4*)(out + zo)     = co;
            *(float4*)(out_bar + zo) = q;
        }
    }
}

// ---------------------------------------------------------------------------
extern "C" void kernel_launch(void* const* d_in, const int* in_sizes, int n_in,
                              void* d_out, int out_size) {
    const float* z = (const float*)d_in[0];
    const float* w = (const float*)d_in[1];
    if (n_in >= 2 && in_sizes[0] == KK * CC && in_sizes[1] == NN * CC) {
        const float* t = z; z = w; w = t;
    }
    float* out = (float*)d_out;

    static bool attr_set = false;
    if (!attr_set) {
        cudaFuncSetAttribute(vq_gemm_kernel, cudaFuncAttributeMaxDynamicSharedMemorySize,
                             SMEM_TOTAL);
        cudaFuncSetAttribute(epilogue_kernel, cudaFuncAttributeMaxDynamicSharedMemorySize,
                             EPI_SMEM);
        attr_set = true;
    }

    prep_w_kernel<<<KK / 8, 256>>>(w);
    zprep_kernel<<<dim3(CC / 32, HWD / 32, BB), dim3(32, 8)>>>(z);
    vq_gemm_kernel<<<NN / BM, 512, SMEM_TOTAL>>>();
    argmin_kernel<<<NN / 8, 256>>>(w);
    epilogue_kernel<<<NN / BM, 512, EPI_SMEM>>>(z, w, out);
}